// round 11
// baseline (speedup 1.0000x reference)
#include <cuda_runtime.h>
#include <cuda_fp16.h>
#include <cstdint>
#include <math.h>

#define BSZ 32
#define TT  2048
#define EP  512
#define AD  512
#define NCH 32
#define FILT 100
#define KW  201

// output layout: c_v (32*512), w (32*2048), h_new (32*512), c_new (32*512)
#define OUT_CV 0
#define OUT_W  (BSZ*EP)            // 16384
#define OUT_H  (OUT_W + BSZ*TT)    // 81920
#define OUT_C  (OUT_H + BSZ*AD)    // 98304

__device__ float g_featT[NCH*BSZ];         // [c][b]
__device__ float g_hT[AD*BSZ];             // att_h transposed [k][b]
__device__ float g_gates[BSZ*4*AD];
__device__ float g_bias[BSZ*AD];
__device__ float g_score[BSZ*TT];
__device__ float g_h[BSZ*AD];

// A = enc rounded to fp16, row-major (B*T, 512)
__device__ __half g_Ahalf[(size_t)BSZ*TT*EP];
// B = V_w^T rounded to fp16, n-major: (512 n-rows, 512 k-cols)
__device__ __half g_Bh[(size_t)AD*EP];

// ===========================================================================
// helpers
// ===========================================================================
__device__ __forceinline__ uint32_t smem_to_u32(const void* p) {
    uint32_t a;
    asm("{ .reg .u64 t; cvta.to.shared.u64 t, %1; cvt.u32.u64 %0, t; }" : "=r"(a) : "l"(p));
    return a;
}
__device__ __forceinline__ void cp_async16(uint32_t dst, const void* src) {
    asm volatile("cp.async.cg.shared.global [%0], [%1], 16;" :: "r"(dst), "l"(src));
}
__device__ __forceinline__ void cp_commit() {
    asm volatile("cp.async.commit_group;" ::: "memory");
}
__device__ __forceinline__ void ldsm4(uint32_t r[4], uint32_t addr) {
    asm volatile("ldmatrix.sync.aligned.m8n8.x4.shared.b16 {%0,%1,%2,%3}, [%4];"
        : "=r"(r[0]), "=r"(r[1]), "=r"(r[2]), "=r"(r[3]) : "r"(addr));
}
__device__ __forceinline__ void mma16816(float d[4], const uint32_t a[4],
                                         uint32_t b0, uint32_t b1) {
    asm volatile("mma.sync.aligned.m16n8k16.row.col.f32.f16.f16.f32 "
        "{%0,%1,%2,%3}, {%4,%5,%6,%7}, {%8,%9}, {%0,%1,%2,%3};"
        : "+f"(d[0]), "+f"(d[1]), "+f"(d[2]), "+f"(d[3])
        : "r"(a[0]), "r"(a[1]), "r"(a[2]), "r"(a[3]), "r"(b0), "r"(b1));
}

// FMA-only tanh: exp2 poly + bit-ldexp + magic-seed Newton reciprocal.
// abs err < ~1e-5; avoids MUFU (chip MUFU throughput is a wall at 33.5M calls).
__device__ __forceinline__ float fast_tanh(float x) {
    float ax = fminf(fabsf(x), 9.0f);
    float y = ax * 2.885390082f;                 // 2x * log2(e)
    float n = rintf(y);
    float f = y - n;
    float p = 1.3333558e-3f;
    p = fmaf(p, f, 9.6181291e-3f);
    p = fmaf(p, f, 5.5504109e-2f);
    p = fmaf(p, f, 2.4022651e-1f);
    p = fmaf(p, f, 6.9314718e-1f);
    p = fmaf(p, f, 1.0f);
    float z = __int_as_float(__float_as_int(p) + ((int)n << 23));   // e^{2ax}
    float d = z + 1.0f;
    float r = __int_as_float(0x7EF311C3u - __float_as_uint(d));     // ~1/d
    r = r * (2.0f - d * r);
    r = r * (2.0f - d * r);
    float t = (z - 1.0f) * r;
    return __int_as_float(__float_as_int(t) | (__float_as_int(x) & 0x80000000));
}

// ===========================================================================
// K0: enc -> fp16 (A); V_w -> fp16 transposed (B); zero g_score;
// g_gates = b_ih+b_hh; att_h -> transposed. One launch.
// ===========================================================================
__global__ __launch_bounds__(256) void convAB_kernel(
    const float* __restrict__ enc, const float* __restrict__ Vw,
    const float* __restrict__ b_ih, const float* __restrict__ b_hh,
    const float* __restrict__ att_h)
{
    int i4 = blockIdx.x * 256 + threadIdx.x;        // 8,388,608 threads
    if (i4 < BSZ*TT) g_score[i4] = 0.f;
    if (i4 < EP*AD) {
        int k = i4 >> 9, n = i4 & 511;
        g_Bh[(size_t)n*EP + k] = __float2half_rn(Vw[i4]);
    }
    if (i4 < BSZ*4*AD) {
        int j = i4 & (4*AD - 1);
        g_gates[i4] = b_ih[j] + b_hh[j];
    }
    if (i4 < AD*BSZ) {
        int k = i4 >> 5, b = i4 & 31;
        g_hT[i4] = att_h[b*AD + k];
    }
    size_t base = (size_t)i4 * 4;
    float4 v = *reinterpret_cast<const float4*>(enc + base);
    __half2 h01 = __floats2half2_rn(v.x, v.y);
    __half2 h23 = __floats2half2_rn(v.z, v.w);
    *reinterpret_cast<uint2*>(g_Ahalf + base) =
        make_uint2(*reinterpret_cast<uint32_t*>(&h01), *reinterpret_cast<uint32_t*>(&h23));
}

// ===========================================================================
// K1: location conv (201 taps) + relu + max-pool -> featT.
// Register-tiled FIR: thread owns 8 consecutive t; 8 channels per block.
// ===========================================================================
#define CG 8
#define XPAD (TT + 2*FILT + 8)     // 2256 floats, zero-padded
__global__ __launch_bounds__(256) void conv_max_kernel(
    const float* __restrict__ att_prev, const float* __restrict__ conv_w)
{
    int b = blockIdx.x, cg = blockIdx.y;
    __shared__ float xs[XPAD];
    __shared__ float ws[CG][KW + 1];
    __shared__ float red[CG * 8];
    int tid = threadIdx.x;
    for (int i = tid; i < XPAD; i += 256)
        xs[i] = (i >= FILT && i < FILT + TT) ? att_prev[b*TT + i - FILT] : 0.f;
    for (int i = tid; i < CG*KW; i += 256)
        ws[i / KW][i % KW] = conv_w[(cg*CG + i/KW)*KW + (i % KW)];
    __syncthreads();

    int t0 = tid * 8;
    float acc[CG][8];
    #pragma unroll
    for (int c = 0; c < CG; c++)
        #pragma unroll
        for (int i = 0; i < 8; i++) acc[c][i] = 0.f;

    for (int kb = 0; kb < 200; kb += 8) {
        float xw[16];
        const float4* xp = reinterpret_cast<const float4*>(xs + t0 + kb);
        *reinterpret_cast<float4*>(xw + 0)  = xp[0];
        *reinterpret_cast<float4*>(xw + 4)  = xp[1];
        *reinterpret_cast<float4*>(xw + 8)  = xp[2];
        *reinterpret_cast<float4*>(xw + 12) = xp[3];
        #pragma unroll
        for (int c = 0; c < CG; c++)
            #pragma unroll
            for (int j = 0; j < 8; j++) {
                float w = ws[c][kb + j];
                #pragma unroll
                for (int i = 0; i < 8; i++)
                    acc[c][i] = fmaf(w, xw[j + i], acc[c][i]);
            }
    }
    {   // k = 200
        float xw[8];
        const float4* xp = reinterpret_cast<const float4*>(xs + t0 + 200);
        *reinterpret_cast<float4*>(xw + 0) = xp[0];
        *reinterpret_cast<float4*>(xw + 4) = xp[1];
        #pragma unroll
        for (int c = 0; c < CG; c++) {
            float w = ws[c][200];
            #pragma unroll
            for (int i = 0; i < 8; i++)
                acc[c][i] = fmaf(w, xw[i], acc[c][i]);
        }
    }

    int lane = tid & 31, warp = tid >> 5;
    #pragma unroll
    for (int c = 0; c < CG; c++) {
        float m = 0.f;
        #pragma unroll
        for (int i = 0; i < 8; i++) m = fmaxf(m, acc[c][i]);
        #pragma unroll
        for (int o = 16; o > 0; o >>= 1)
            m = fmaxf(m, __shfl_xor_sync(0xffffffffu, m, o));
        if (lane == 0) red[c*8 + warp] = m;
    }
    __syncthreads();
    if (tid < CG) {
        float m = red[tid*8];
        #pragma unroll
        for (int wp = 1; wp < 8; wp++) m = fmaxf(m, red[tid*8 + wp]);
        g_featT[(cg*CG + tid)*BSZ + b] = m;
    }
}

// ===========================================================================
// K2: LSTM gates, transposed-operand form: warp = (j, ks), lanes = b.
// ===========================================================================
__global__ __launch_bounds__(256) void gates_kernel(
    const float* __restrict__ W_ih, const float* __restrict__ W_hh)
{
    int w = blockIdx.x * 8 + (threadIdx.x >> 5);
    int lane = threadIdx.x & 31;        // = b
    int j = w >> 2, ks = w & 3;
    const float4* wr = reinterpret_cast<const float4*>(W_hh + (size_t)j*AD + ks*128);
    const float* ht = g_hT + ks*128*BSZ + lane;
    float s0 = 0.f, s1 = 0.f, s2 = 0.f, s3 = 0.f;
    #pragma unroll
    for (int k = 0; k < 32; k++) {
        float4 wv = __ldg(wr + k);
        s0 = fmaf(wv.x, ht[(4*k+0)*BSZ], s0);
        s1 = fmaf(wv.y, ht[(4*k+1)*BSZ], s1);
        s2 = fmaf(wv.z, ht[(4*k+2)*BSZ], s2);
        s3 = fmaf(wv.w, ht[(4*k+3)*BSZ], s3);
    }
    float s = s0 + s1 + s2 + s3;
    if (ks == 0) {
        const float* wi = W_ih + j*NCH;
        #pragma unroll
        for (int c = 0; c < NCH; c++)
            s = fmaf(__ldg(wi + c), g_featT[c*BSZ + lane], s);
    }
    atomicAdd(&g_gates[lane*4*AD + j], s);
}

// ===========================================================================
// K2b: LSTM elementwise -> h_new, c_new; init c_v=0 and g_bias=const
// ===========================================================================
__global__ __launch_bounds__(256) void lstm_kernel(
    const float* __restrict__ att_c, float* __restrict__ out,
    const float* __restrict__ W_b, const float* __restrict__ U_b,
    const float* __restrict__ V_b)
{
    int idx = blockIdx.x * 256 + threadIdx.x;
    if (idx >= BSZ*AD) return;
    int b = idx / AD, a = idx % AD;
    const float* g = g_gates + b*4*AD;
    float gi = g[a], gf = g[AD + a], gg = g[2*AD + a], go = g[3*AD + a];
    float si = 1.f / (1.f + expf(-gi));
    float sf = 1.f / (1.f + expf(-gf));
    float so = 1.f / (1.f + expf(-go));
    float cn = sf * att_c[idx] + si * tanhf(gg);
    float hn = so * tanhf(cn);
    g_h[idx] = hn;
    out[OUT_H + idx] = hn;
    out[OUT_C + idx] = cn;
    out[OUT_CV + idx] = 0.f;
    g_bias[idx] = W_b[a] + U_b[a] + V_b[a];   // bias_kernel atomically adds on top
}

// ===========================================================================
// K3: bias[b,a] += h_new·W_w[:,a] + dec_z·U_w[:,a]  (k-split, atomic)
// ===========================================================================
__global__ __launch_bounds__(128) void bias_kernel(
    const float* __restrict__ dec_z, const float* __restrict__ W_w,
    const float* __restrict__ U_w)
{
    int a  = blockIdx.x * 128 + threadIdx.x;
    int b  = blockIdx.y;
    int k0 = blockIdx.z * 128;
    __shared__ float hs[128], zs[128];
    hs[threadIdx.x] = g_h[b*AD + k0 + threadIdx.x];
    zs[threadIdx.x] = dec_z[b*AD + k0 + threadIdx.x];
    __syncthreads();
    float s = 0.f;
    #pragma unroll 8
    for (int k = 0; k < 128; k++)
        s += hs[k] * W_w[(size_t)(k0 + k)*AD + a] + zs[k] * U_w[(size_t)(k0 + k)*AD + a];
    atomicAdd(&g_bias[b*AD + a], s);
}

// ===========================================================================
// K4: PERSISTENT mma.sync fp16 score GEMM + fused tanh/g-dot epilogue.
// grid 296 (2 CTA/SM), tile loop over 512 tiles -> no tail wave.
// CTA tile 128x128; BK=64 chunks double-buffered via cp.async.
// ===========================================================================
#define ASTR 72                      // fp16 elems per smem row (144B: conflict-free ldmatrix)
#define CHUNK_B (128*ASTR*2)         // 18432 bytes per 128x64 chunk
#define SCORE_SMEM (4*CHUNK_B)       // 2 stages x {A,B} = 73728 B
#define NTILES ((BSZ*TT/128) * 4)    // 512
#define SCORE_GRID 296

__device__ __forceinline__ void compute_chunk(
    uint32_t aBase, uint32_t bBase, int warp_m, int warp_n, int lane,
    float (&acc)[4][4][4])
{
    int rsel = lane & 15, csel = (lane >> 4) * 8;
    #pragma unroll
    for (int ks = 0; ks < 4; ks++) {
        uint32_t a[4][4], bq[2][4];
        #pragma unroll
        for (int mt = 0; mt < 4; mt++) {
            uint32_t addr = aBase + ((warp_m*64 + mt*16 + rsel)*ASTR + csel + ks*16)*2;
            ldsm4(a[mt], addr);
        }
        #pragma unroll
        for (int np = 0; np < 2; np++) {
            uint32_t addr = bBase + ((warp_n*32 + np*16 + rsel)*ASTR + csel + ks*16)*2;
            ldsm4(bq[np], addr);
        }
        #pragma unroll
        for (int mt = 0; mt < 4; mt++)
            #pragma unroll
            for (int nt = 0; nt < 4; nt++)
                mma16816(acc[mt][nt], a[mt], bq[nt>>1][nt&1], bq[nt>>1][2+(nt&1)]);
    }
}

__global__ __launch_bounds__(256, 2) void score_mma_kernel(const float* __restrict__ gw)
{
    extern __shared__ char smem[];
    uint32_t smem_base = smem_to_u32(smem);
    int tid = threadIdx.x, lane = tid & 31, wid = tid >> 5;
    int warp_m = wid & 1, warp_n = wid >> 1;

    for (int tile = blockIdx.x; tile < NTILES; tile += SCORE_GRID) {
        int mtile = tile >> 2, ntile = tile & 3;   // concurrent tiles share A in L2
        int row0 = mtile * 128, n0 = ntile * 128;
        int b = row0 / TT;

        float acc[4][4][4];
        #pragma unroll
        for (int mt = 0; mt < 4; mt++)
            #pragma unroll
            for (int nt = 0; nt < 4; nt++)
                #pragma unroll
                for (int i = 0; i < 4; i++) acc[mt][nt][i] = 0.f;

        const __half* Arow = g_Ahalf + (size_t)row0 * EP;
        const __half* Brow = g_Bh + (size_t)n0 * EP;

        auto load_set = [&](int s, int kc) {
            uint32_t ah = smem_base + (uint32_t)(s*2 + 0) * CHUNK_B;
            uint32_t bh = smem_base + (uint32_t)(s*2 + 1) * CHUNK_B;
            const __half* Aq = Arow + kc*64;
            const __half* Bq = Brow + kc*64;
            #pragma unroll
            for (int j = 0; j < 4; j++) {
                int p = tid + 256*j;
                int r = p >> 3, q = p & 7;
                cp_async16(ah + (r*ASTR + q*8)*2, Aq + (size_t)r*EP + q*8);
                cp_async16(bh + (r*ASTR + q*8)*2, Bq + (size_t)r*EP + q*8);
            }
            cp_commit();
        };

        load_set(0, 0);
        for (int kc = 0; kc < 8; kc++) {
            if (kc + 1 < 8) {
                load_set((kc + 1) & 1, kc + 1);
                asm volatile("cp.async.wait_group 1;" ::: "memory");
            } else {
                asm volatile("cp.async.wait_group 0;" ::: "memory");
            }
            __syncthreads();
            int s = kc & 1;
            uint32_t Ah = smem_base + (uint32_t)(s*2 + 0) * CHUNK_B;
            uint32_t Bh = smem_base + (uint32_t)(s*2 + 1) * CHUNK_B;
            compute_chunk(Ah, Bh, warp_m, warp_n, lane, acc);
            __syncthreads();
        }

        // epilogue: rowsum += g[n]*tanh(acc + bias[b,n]); reduce 4 q-lanes
        int gq = lane >> 2, q = lane & 3;
        float gv[8], bb[8];
        #pragma unroll
        for (int nt = 0; nt < 4; nt++)
            #pragma unroll
            for (int h = 0; h < 2; h++) {
                int n = n0 + warp_n*32 + nt*8 + q*2 + h;
                gv[nt*2 + h] = __ldg(gw + n);
                bb[nt*2 + h] = g_bias[b*AD + n];
            }
        #pragma unroll
        for (int mt = 0; mt < 4; mt++) {
            float p0 = 0.f, p1 = 0.f;
            #pragma unroll
            for (int nt = 0; nt < 4; nt++) {
                p0 += gv[nt*2+0] * fast_tanh(acc[mt][nt][0] + bb[nt*2+0]);
                p0 += gv[nt*2+1] * fast_tanh(acc[mt][nt][1] + bb[nt*2+1]);
                p1 += gv[nt*2+0] * fast_tanh(acc[mt][nt][2] + bb[nt*2+0]);
                p1 += gv[nt*2+1] * fast_tanh(acc[mt][nt][3] + bb[nt*2+1]);
            }
            p0 += __shfl_xor_sync(0xffffffffu, p0, 1);
            p0 += __shfl_xor_sync(0xffffffffu, p0, 2);
            p1 += __shfl_xor_sync(0xffffffffu, p1, 1);
            p1 += __shfl_xor_sync(0xffffffffu, p1, 2);
            if (q == 0) {
                atomicAdd(&g_score[row0 + warp_m*64 + mt*16 + gq],     p0);
                atomicAdd(&g_score[row0 + warp_m*64 + mt*16 + 8 + gq], p1);
            }
        }
        __syncthreads();   // isolate epilogue from next tile's smem stores
    }
}

// ===========================================================================
// K5: masked, scaled softmax over T per batch -> w (g_b dropped: shift-invariant)
// ===========================================================================
__global__ __launch_bounds__(256) void softmax_kernel(
    const int* __restrict__ len, float* __restrict__ out)
{
    int b = blockIdx.x;
    int L = len[b];
    __shared__ float red[256];
    float* wout = out + OUT_W + b*TT;

    float mx = -3.0e38f;
    for (int t = threadIdx.x; t < TT; t += 256) {
        float v = (t < L) ? 2.0f * g_score[b*TT + t] : -3.0e38f;
        mx = fmaxf(mx, v);
    }
    red[threadIdx.x] = mx; __syncthreads();
    for (int s = 128; s > 0; s >>= 1) {
        if (threadIdx.x < s) red[threadIdx.x] = fmaxf(red[threadIdx.x], red[threadIdx.x + s]);
        __syncthreads();
    }
    mx = red[0]; __syncthreads();

    float sum = 0.f;
    for (int t = threadIdx.x; t < TT; t += 256) {
        float p = (t < L) ? expf(2.0f * g_score[b*TT + t] - mx) : 0.f;
        wout[t] = p;
        sum += p;
    }
    red[threadIdx.x] = sum; __syncthreads();
    for (int s = 128; s > 0; s >>= 1) {
        if (threadIdx.x < s) red[threadIdx.x] += red[threadIdx.x + s];
        __syncthreads();
    }
    float inv = 1.0f / red[0];
    for (int t = threadIdx.x; t < TT; t += 256) wout[t] *= inv;
}

// ===========================================================================
// K6: context c_v[b,e] = sum_t w[b,t]*enc16[b,t,e]  (fp16 enc: half traffic)
// ===========================================================================
__global__ __launch_bounds__(128) void context_kernel(float* __restrict__ out)
{
    int b = blockIdx.z;
    int e0 = blockIdx.x * 256 + threadIdx.x * 2;
    int t0 = blockIdx.y * 256;
    const float* wrow = out + OUT_W + b*TT + t0;
    const __half* ep = g_Ahalf + ((size_t)b*TT + t0)*EP + e0;
    float s0 = 0.f, s1 = 0.f;
    #pragma unroll 8
    for (int t = 0; t < 256; t++) {
        float wv = __ldg(wrow + t);
        __half2 h = *reinterpret_cast<const __half2*>(ep + (size_t)t*EP);
        float2 v = __half22float2(h);
        s0 = fmaf(wv, v.x, s0);
        s1 = fmaf(wv, v.y, s1);
    }
    atomicAdd(&out[OUT_CV + b*EP + e0],     s0);
    atomicAdd(&out[OUT_CV + b*EP + e0 + 1], s1);
}

// ===========================================================================
extern "C" void kernel_launch(void* const* d_in, const int* in_sizes, int n_in,
                              void* d_out, int out_size)
{
    const float* enc      = (const float*)d_in[0];
    const int*   enc_len  = (const int*)  d_in[1];
    const float* dec_z    = (const float*)d_in[2];
    const float* att_prev = (const float*)d_in[3];
    const float* att_h    = (const float*)d_in[4];
    const float* att_c    = (const float*)d_in[5];
    const float* W_w      = (const float*)d_in[6];
    const float* W_b      = (const float*)d_in[7];
    const float* V_w      = (const float*)d_in[8];
    const float* V_b      = (const float*)d_in[9];
    const float* U_w      = (const float*)d_in[10];
    const float* U_b      = (const float*)d_in[11];
    const float* g_w      = (const float*)d_in[12];
    const float* g_b      = (const float*)d_in[13];  // unused: softmax shift-invariant
    const float* conv_w   = (const float*)d_in[14];
    const float* W_ih     = (const float*)d_in[15];
    const float* W_hh     = (const float*)d_in[16];
    const float* b_ih     = (const float*)d_in[17];
    const float* b_hh     = (const float*)d_in[18];
    float* out = (float*)d_out;
    (void)g_b;

    cudaFuncSetAttribute(score_mma_kernel, cudaFuncAttributeMaxDynamicSharedMemorySize, SCORE_SMEM);

    // K0: enc->fp16, V_w->fp16^T, zero g_score, g_gates=bias, att_h^T
    convAB_kernel<<<(BSZ*TT*EP/4) / 256, 256>>>(enc, V_w, b_ih, b_hh, att_h);
    // K1: register-tiled conv + relu + maxpool -> featT (8 ch/block)
    conv_max_kernel<<<dim3(BSZ, NCH/CG), 256>>>(att_prev, conv_w);
    // K2: LSTM gates (transposed, k-split, atomic)
    gates_kernel<<<1024, 256>>>(W_ih, W_hh);
    // K2b: LSTM cell elementwise (+ zero c_v, init g_bias const)
    lstm_kernel<<<(BSZ*AD + 255) / 256, 256>>>(att_c, out, W_b, U_b, V_b);
    // K3: per-batch additive bias (wh + dec_proj), k-split atomic
    bias_kernel<<<dim3(4, BSZ, 4), 128>>>(dec_z, W_w, U_w);
    // K4: persistent single-pass fp16 GEMM + tanh/g-dot -> score
    score_mma_kernel<<<SCORE_GRID, 256, SCORE_SMEM>>>(g_w);
    // K5: masked scaled softmax -> w
    softmax_kernel<<<BSZ, 256>>>(enc_len, out);
    // K6: context vector (fp16 enc)
    context_kernel<<<dim3(2, 8, BSZ), 128>>>(out);
}

// round 12
// speedup vs baseline: 1.0511x; 1.0511x over previous
#include <cuda_runtime.h>
#include <cuda_fp16.h>
#include <cstdint>
#include <math.h>

#define BSZ 32
#define TT  2048
#define EP  512
#define AD  512
#define NCH 32
#define FILT 100
#define KW  201

// output layout: c_v (32*512), w (32*2048), h_new (32*512), c_new (32*512)
#define OUT_CV 0
#define OUT_W  (BSZ*EP)            // 16384
#define OUT_H  (OUT_W + BSZ*TT)    // 81920
#define OUT_C  (OUT_H + BSZ*AD)    // 98304

__device__ float g_featT[NCH*BSZ];         // [c][b]
__device__ float g_hT[AD*BSZ];             // att_h transposed [k][b]
__device__ float g_gates[BSZ*4*AD];
__device__ float g_bias[BSZ*AD];
__device__ float g_score[BSZ*TT];

// A = enc rounded to fp16, row-major (B*T, 512)
__device__ __half g_Ahalf[(size_t)BSZ*TT*EP];
// B = V_w^T rounded to fp16, n-major: (512 n-rows, 512 k-cols)
__device__ __half g_Bh[(size_t)AD*EP];

// ===========================================================================
// helpers
// ===========================================================================
__device__ __forceinline__ uint32_t smem_to_u32(const void* p) {
    uint32_t a;
    asm("{ .reg .u64 t; cvta.to.shared.u64 t, %1; cvt.u32.u64 %0, t; }" : "=r"(a) : "l"(p));
    return a;
}
__device__ __forceinline__ void cp_async16(uint32_t dst, const void* src) {
    asm volatile("cp.async.cg.shared.global [%0], [%1], 16;" :: "r"(dst), "l"(src));
}
__device__ __forceinline__ void cp_commit() {
    asm volatile("cp.async.commit_group;" ::: "memory");
}
__device__ __forceinline__ void ldsm4(uint32_t r[4], uint32_t addr) {
    asm volatile("ldmatrix.sync.aligned.m8n8.x4.shared.b16 {%0,%1,%2,%3}, [%4];"
        : "=r"(r[0]), "=r"(r[1]), "=r"(r[2]), "=r"(r[3]) : "r"(addr));
}
__device__ __forceinline__ void mma16816(float d[4], const uint32_t a[4],
                                         uint32_t b0, uint32_t b1) {
    asm volatile("mma.sync.aligned.m16n8k16.row.col.f32.f16.f16.f32 "
        "{%0,%1,%2,%3}, {%4,%5,%6,%7}, {%8,%9}, {%0,%1,%2,%3};"
        : "+f"(d[0]), "+f"(d[1]), "+f"(d[2]), "+f"(d[3])
        : "r"(a[0]), "r"(a[1]), "r"(a[2]), "r"(a[3]), "r"(b0), "r"(b1));
}

// FMA-only tanh: exp2 poly + bit-ldexp + magic-seed Newton reciprocal.
// abs err < ~1e-5; avoids MUFU (chip MUFU throughput is a wall at 33.5M calls).
__device__ __forceinline__ float fast_tanh(float x) {
    float ax = fminf(fabsf(x), 9.0f);
    float y = ax * 2.885390082f;                 // 2x * log2(e)
    float n = rintf(y);
    float f = y - n;
    float p = 1.3333558e-3f;
    p = fmaf(p, f, 9.6181291e-3f);
    p = fmaf(p, f, 5.5504109e-2f);
    p = fmaf(p, f, 2.4022651e-1f);
    p = fmaf(p, f, 6.9314718e-1f);
    p = fmaf(p, f, 1.0f);
    float z = __int_as_float(__float_as_int(p) + ((int)n << 23));   // e^{2ax}
    float d = z + 1.0f;
    float r = __int_as_float(0x7EF311C3u - __float_as_uint(d));     // ~1/d
    r = r * (2.0f - d * r);
    r = r * (2.0f - d * r);
    float t = (z - 1.0f) * r;
    return __int_as_float(__float_as_int(t) | (__float_as_int(x) & 0x80000000));
}

// ===========================================================================
// K0: enc -> fp16 (A); V_w -> fp16 transposed (B); zero g_score + c_v;
// g_gates = b_ih+b_hh; g_bias = W_b+U_b+V_b; att_h -> transposed. One launch.
// ===========================================================================
__global__ __launch_bounds__(256) void convAB_kernel(
    const float* __restrict__ enc, const float* __restrict__ Vw,
    const float* __restrict__ b_ih, const float* __restrict__ b_hh,
    const float* __restrict__ att_h, const float* __restrict__ W_b,
    const float* __restrict__ U_b, const float* __restrict__ V_b,
    float* __restrict__ out)
{
    int i4 = blockIdx.x * 256 + threadIdx.x;        // 8,388,608 threads
    if (i4 < BSZ*TT) g_score[i4] = 0.f;
    if (i4 < EP*AD) {
        int k = i4 >> 9, n = i4 & 511;
        g_Bh[(size_t)n*EP + k] = __float2half_rn(Vw[i4]);
    }
    if (i4 < BSZ*4*AD) {
        int j = i4 & (4*AD - 1);
        g_gates[i4] = b_ih[j] + b_hh[j];
    }
    if (i4 < AD*BSZ) {
        int k = i4 >> 5, b = i4 & 31;
        g_hT[i4] = att_h[b*AD + k];
    }
    if (i4 < BSZ*AD) {
        int a = i4 & 511;
        g_bias[i4] = W_b[a] + U_b[a] + V_b[a];   // bias atomics add on top
        out[OUT_CV + i4] = 0.f;                  // zero c_v for K6 atomics
    }
    size_t base = (size_t)i4 * 4;
    float4 v = *reinterpret_cast<const float4*>(enc + base);
    __half2 h01 = __floats2half2_rn(v.x, v.y);
    __half2 h23 = __floats2half2_rn(v.z, v.w);
    *reinterpret_cast<uint2*>(g_Ahalf + base) =
        make_uint2(*reinterpret_cast<uint32_t*>(&h01), *reinterpret_cast<uint32_t*>(&h23));
}

// ===========================================================================
// K1: location conv (201 taps) + relu + max-pool -> featT.
// Register-tiled FIR: thread owns 8 consecutive t; 8 channels per block.
// ===========================================================================
#define CG 8
#define XPAD (TT + 2*FILT + 8)     // 2256 floats, zero-padded
__global__ __launch_bounds__(256) void conv_max_kernel(
    const float* __restrict__ att_prev, const float* __restrict__ conv_w)
{
    int b = blockIdx.x, cg = blockIdx.y;
    __shared__ float xs[XPAD];
    __shared__ float ws[CG][KW + 1];
    __shared__ float red[CG * 8];
    int tid = threadIdx.x;
    for (int i = tid; i < XPAD; i += 256)
        xs[i] = (i >= FILT && i < FILT + TT) ? att_prev[b*TT + i - FILT] : 0.f;
    for (int i = tid; i < CG*KW; i += 256)
        ws[i / KW][i % KW] = conv_w[(cg*CG + i/KW)*KW + (i % KW)];
    __syncthreads();

    int t0 = tid * 8;
    float acc[CG][8];
    #pragma unroll
    for (int c = 0; c < CG; c++)
        #pragma unroll
        for (int i = 0; i < 8; i++) acc[c][i] = 0.f;

    for (int kb = 0; kb < 200; kb += 8) {
        float xw[16];
        const float4* xp = reinterpret_cast<const float4*>(xs + t0 + kb);
        *reinterpret_cast<float4*>(xw + 0)  = xp[0];
        *reinterpret_cast<float4*>(xw + 4)  = xp[1];
        *reinterpret_cast<float4*>(xw + 8)  = xp[2];
        *reinterpret_cast<float4*>(xw + 12) = xp[3];
        #pragma unroll
        for (int c = 0; c < CG; c++)
            #pragma unroll
            for (int j = 0; j < 8; j++) {
                float w = ws[c][kb + j];
                #pragma unroll
                for (int i = 0; i < 8; i++)
                    acc[c][i] = fmaf(w, xw[j + i], acc[c][i]);
            }
    }
    {   // k = 200
        float xw[8];
        const float4* xp = reinterpret_cast<const float4*>(xs + t0 + 200);
        *reinterpret_cast<float4*>(xw + 0) = xp[0];
        *reinterpret_cast<float4*>(xw + 4) = xp[1];
        #pragma unroll
        for (int c = 0; c < CG; c++) {
            float w = ws[c][200];
            #pragma unroll
            for (int i = 0; i < 8; i++)
                acc[c][i] = fmaf(w, xw[i], acc[c][i]);
        }
    }

    int lane = tid & 31, warp = tid >> 5;
    #pragma unroll
    for (int c = 0; c < CG; c++) {
        float m = 0.f;
        #pragma unroll
        for (int i = 0; i < 8; i++) m = fmaxf(m, acc[c][i]);
        #pragma unroll
        for (int o = 16; o > 0; o >>= 1)
            m = fmaxf(m, __shfl_xor_sync(0xffffffffu, m, o));
        if (lane == 0) red[c*8 + warp] = m;
    }
    __syncthreads();
    if (tid < CG) {
        float m = red[tid*8];
        #pragma unroll
        for (int wp = 1; wp < 8; wp++) m = fmaxf(m, red[tid*8 + wp]);
        g_featT[(cg*CG + tid)*BSZ + b] = m;
    }
}

// ===========================================================================
// K2: LSTM gates, transposed-operand form: warp = (j, ks), lanes = b.
// ===========================================================================
__global__ __launch_bounds__(256) void gates_kernel(
    const float* __restrict__ W_ih, const float* __restrict__ W_hh)
{
    int w = blockIdx.x * 8 + (threadIdx.x >> 5);
    int lane = threadIdx.x & 31;        // = b
    int j = w >> 2, ks = w & 3;
    const float4* wr = reinterpret_cast<const float4*>(W_hh + (size_t)j*AD + ks*128);
    const float* ht = g_hT + ks*128*BSZ + lane;
    float s0 = 0.f, s1 = 0.f, s2 = 0.f, s3 = 0.f;
    #pragma unroll
    for (int k = 0; k < 32; k++) {
        float4 wv = __ldg(wr + k);
        s0 = fmaf(wv.x, ht[(4*k+0)*BSZ], s0);
        s1 = fmaf(wv.y, ht[(4*k+1)*BSZ], s1);
        s2 = fmaf(wv.z, ht[(4*k+2)*BSZ], s2);
        s3 = fmaf(wv.w, ht[(4*k+3)*BSZ], s3);
    }
    float s = s0 + s1 + s2 + s3;
    if (ks == 0) {
        const float* wi = W_ih + j*NCH;
        #pragma unroll
        for (int c = 0; c < NCH; c++)
            s = fmaf(__ldg(wi + c), g_featT[c*BSZ + lane], s);
    }
    atomicAdd(&g_gates[lane*4*AD + j], s);
}

// ===========================================================================
// K3: fused LSTM + bias. grid (4 a-chunks, 32 b, 4 k-chunks), block 128.
// Each block recomputes hs[128] = lstm(b, k0..k0+127) from g_gates (cheap),
// a-chunk-0 blocks also write h_new/c_new outputs. Then bias GEMV k-slice.
// ===========================================================================
__global__ __launch_bounds__(128) void lstm_bias_kernel(
    const float* __restrict__ att_c, const float* __restrict__ dec_z,
    const float* __restrict__ W_w, const float* __restrict__ U_w,
    float* __restrict__ out)
{
    int a  = blockIdx.x * 128 + threadIdx.x;
    int b  = blockIdx.y;
    int k0 = blockIdx.z * 128;
    __shared__ float hs[128], zs[128];
    {
        int idx = b*AD + k0 + threadIdx.x;
        const float* g = g_gates + b*4*AD + k0 + threadIdx.x;
        float gi = g[0], gf = g[AD], gg = g[2*AD], go = g[3*AD];
        float si = 1.f / (1.f + expf(-gi));
        float sf = 1.f / (1.f + expf(-gf));
        float so = 1.f / (1.f + expf(-go));
        float cn = sf * att_c[idx] + si * tanhf(gg);
        float hn = so * tanhf(cn);
        hs[threadIdx.x] = hn;
        zs[threadIdx.x] = dec_z[idx];
        if (blockIdx.x == 0) {
            out[OUT_H + idx] = hn;
            out[OUT_C + idx] = cn;
        }
    }
    __syncthreads();
    float s = 0.f;
    #pragma unroll 8
    for (int k = 0; k < 128; k++)
        s += hs[k] * W_w[(size_t)(k0 + k)*AD + a] + zs[k] * U_w[(size_t)(k0 + k)*AD + a];
    atomicAdd(&g_bias[b*AD + a], s);
}

// ===========================================================================
// K4: mma.sync fp16 score GEMM + fused tanh/g-dot epilogue (512-CTA launch —
// persistent variant measured slower, R11). CTA tile 128x128; BK=64 chunks
// double-buffered via cp.async. 8 warps 2(M)x4(N).
// ===========================================================================
#define ASTR 72                      // fp16 elems per smem row (144B: conflict-free ldmatrix)
#define CHUNK_B (128*ASTR*2)         // 18432 bytes per 128x64 chunk
#define SCORE_SMEM (4*CHUNK_B)       // 2 stages x {A,B} = 73728 B

__device__ __forceinline__ void compute_chunk(
    uint32_t aBase, uint32_t bBase, int warp_m, int warp_n, int lane,
    float (&acc)[4][4][4])
{
    int rsel = lane & 15, csel = (lane >> 4) * 8;
    #pragma unroll
    for (int ks = 0; ks < 4; ks++) {
        uint32_t a[4][4], bq[2][4];
        #pragma unroll
        for (int mt = 0; mt < 4; mt++) {
            uint32_t addr = aBase + ((warp_m*64 + mt*16 + rsel)*ASTR + csel + ks*16)*2;
            ldsm4(a[mt], addr);
        }
        #pragma unroll
        for (int np = 0; np < 2; np++) {
            uint32_t addr = bBase + ((warp_n*32 + np*16 + rsel)*ASTR + csel + ks*16)*2;
            ldsm4(bq[np], addr);
        }
        #pragma unroll
        for (int mt = 0; mt < 4; mt++)
            #pragma unroll
            for (int nt = 0; nt < 4; nt++)
                mma16816(acc[mt][nt], a[mt], bq[nt>>1][nt&1], bq[nt>>1][2+(nt&1)]);
    }
}

__global__ __launch_bounds__(256, 2) void score_mma_kernel(const float* __restrict__ gw)
{
    extern __shared__ char smem[];
    uint32_t smem_base = smem_to_u32(smem);
    int tid = threadIdx.x, lane = tid & 31, wid = tid >> 5;
    int mtile = blockIdx.x >> 2, ntile = blockIdx.x & 3;   // adjacent n-tiles: A reuse in L2
    int row0 = mtile * 128, n0 = ntile * 128;
    int b = row0 / TT;
    int warp_m = wid & 1, warp_n = wid >> 1;

    float acc[4][4][4];
    #pragma unroll
    for (int mt = 0; mt < 4; mt++)
        #pragma unroll
        for (int nt = 0; nt < 4; nt++)
            #pragma unroll
            for (int i = 0; i < 4; i++) acc[mt][nt][i] = 0.f;

    const __half* Arow = g_Ahalf + (size_t)row0 * EP;
    const __half* Brow = g_Bh + (size_t)n0 * EP;

    auto load_set = [&](int s, int kc) {
        uint32_t ah = smem_base + (uint32_t)(s*2 + 0) * CHUNK_B;
        uint32_t bh = smem_base + (uint32_t)(s*2 + 1) * CHUNK_B;
        const __half* Aq = Arow + kc*64;
        const __half* Bq = Brow + kc*64;
        #pragma unroll
        for (int j = 0; j < 4; j++) {
            int p = tid + 256*j;
            int r = p >> 3, q = p & 7;
            cp_async16(ah + (r*ASTR + q*8)*2, Aq + (size_t)r*EP + q*8);
            cp_async16(bh + (r*ASTR + q*8)*2, Bq + (size_t)r*EP + q*8);
        }
        cp_commit();
    };

    load_set(0, 0);
    for (int kc = 0; kc < 8; kc++) {
        if (kc + 1 < 8) {
            load_set((kc + 1) & 1, kc + 1);
            asm volatile("cp.async.wait_group 1;" ::: "memory");
        } else {
            asm volatile("cp.async.wait_group 0;" ::: "memory");
        }
        __syncthreads();
        int s = kc & 1;
        uint32_t Ah = smem_base + (uint32_t)(s*2 + 0) * CHUNK_B;
        uint32_t Bh = smem_base + (uint32_t)(s*2 + 1) * CHUNK_B;
        compute_chunk(Ah, Bh, warp_m, warp_n, lane, acc);
        __syncthreads();
    }

    // epilogue: rowsum += g[n]*tanh(acc + bias[b,n]); reduce 4 q-lanes; atomic
    int gq = lane >> 2, q = lane & 3;
    float gv[8], bb[8];
    #pragma unroll
    for (int nt = 0; nt < 4; nt++)
        #pragma unroll
        for (int h = 0; h < 2; h++) {
            int n = n0 + warp_n*32 + nt*8 + q*2 + h;
            gv[nt*2 + h] = __ldg(gw + n);
            bb[nt*2 + h] = g_bias[b*AD + n];
        }
    #pragma unroll
    for (int mt = 0; mt < 4; mt++) {
        float p0 = 0.f, p1 = 0.f;
        #pragma unroll
        for (int nt = 0; nt < 4; nt++) {
            p0 += gv[nt*2+0] * fast_tanh(acc[mt][nt][0] + bb[nt*2+0]);
            p0 += gv[nt*2+1] * fast_tanh(acc[mt][nt][1] + bb[nt*2+1]);
            p1 += gv[nt*2+0] * fast_tanh(acc[mt][nt][2] + bb[nt*2+0]);
            p1 += gv[nt*2+1] * fast_tanh(acc[mt][nt][3] + bb[nt*2+1]);
        }
        p0 += __shfl_xor_sync(0xffffffffu, p0, 1);
        p0 += __shfl_xor_sync(0xffffffffu, p0, 2);
        p1 += __shfl_xor_sync(0xffffffffu, p1, 1);
        p1 += __shfl_xor_sync(0xffffffffu, p1, 2);
        if (q == 0) {
            atomicAdd(&g_score[row0 + warp_m*64 + mt*16 + gq],     p0);
            atomicAdd(&g_score[row0 + warp_m*64 + mt*16 + 8 + gq], p1);
        }
    }
}

// ===========================================================================
// K5: masked, scaled softmax over T per batch -> w (g_b dropped: shift-invariant)
// ===========================================================================
__global__ __launch_bounds__(256) void softmax_kernel(
    const int* __restrict__ len, float* __restrict__ out)
{
    int b = blockIdx.x;
    int L = len[b];
    __shared__ float red[256];
    float* wout = out + OUT_W + b*TT;

    float mx = -3.0e38f;
    for (int t = threadIdx.x; t < TT; t += 256) {
        float v = (t < L) ? 2.0f * g_score[b*TT + t] : -3.0e38f;
        mx = fmaxf(mx, v);
    }
    red[threadIdx.x] = mx; __syncthreads();
    for (int s = 128; s > 0; s >>= 1) {
        if (threadIdx.x < s) red[threadIdx.x] = fmaxf(red[threadIdx.x], red[threadIdx.x + s]);
        __syncthreads();
    }
    mx = red[0]; __syncthreads();

    float sum = 0.f;
    for (int t = threadIdx.x; t < TT; t += 256) {
        float p = (t < L) ? expf(2.0f * g_score[b*TT + t] - mx) : 0.f;
        wout[t] = p;
        sum += p;
    }
    red[threadIdx.x] = sum; __syncthreads();
    for (int s = 128; s > 0; s >>= 1) {
        if (threadIdx.x < s) red[threadIdx.x] += red[threadIdx.x + s];
        __syncthreads();
    }
    float inv = 1.0f / red[0];
    for (int t = threadIdx.x; t < TT; t += 256) wout[t] *= inv;
}

// ===========================================================================
// K6: context c_v[b,e] = sum_t w[b,t]*enc16[b,t,e]  (fp16 enc: half traffic)
// ===========================================================================
__global__ __launch_bounds__(128) void context_kernel(float* __restrict__ out)
{
    int b = blockIdx.z;
    int e0 = blockIdx.x * 256 + threadIdx.x * 2;
    int t0 = blockIdx.y * 256;
    const float* wrow = out + OUT_W + b*TT + t0;
    const __half* ep = g_Ahalf + ((size_t)b*TT + t0)*EP + e0;
    float s0 = 0.f, s1 = 0.f;
    #pragma unroll 8
    for (int t = 0; t < 256; t++) {
        float wv = __ldg(wrow + t);
        __half2 h = *reinterpret_cast<const __half2*>(ep + (size_t)t*EP);
        float2 v = __half22float2(h);
        s0 = fmaf(wv, v.x, s0);
        s1 = fmaf(wv, v.y, s1);
    }
    atomicAdd(&out[OUT_CV + b*EP + e0],     s0);
    atomicAdd(&out[OUT_CV + b*EP + e0 + 1], s1);
}

// ===========================================================================
extern "C" void kernel_launch(void* const* d_in, const int* in_sizes, int n_in,
                              void* d_out, int out_size)
{
    const float* enc      = (const float*)d_in[0];
    const int*   enc_len  = (const int*)  d_in[1];
    const float* dec_z    = (const float*)d_in[2];
    const float* att_prev = (const float*)d_in[3];
    const float* att_h    = (const float*)d_in[4];
    const float* att_c    = (const float*)d_in[5];
    const float* W_w      = (const float*)d_in[6];
    const float* W_b      = (const float*)d_in[7];
    const float* V_w      = (const float*)d_in[8];
    const float* V_b      = (const float*)d_in[9];
    const float* U_w      = (const float*)d_in[10];
    const float* U_b      = (const float*)d_in[11];
    const float* g_w      = (const float*)d_in[12];
    const float* g_b      = (const float*)d_in[13];  // unused: softmax shift-invariant
    const float* conv_w   = (const float*)d_in[14];
    const float* W_ih     = (const float*)d_in[15];
    const float* W_hh     = (const float*)d_in[16];
    const float* b_ih     = (const float*)d_in[17];
    const float* b_hh     = (const float*)d_in[18];
    float* out = (float*)d_out;
    (void)g_b;

    cudaFuncSetAttribute(score_mma_kernel, cudaFuncAttributeMaxDynamicSharedMemorySize, SCORE_SMEM);

    // K0: enc->fp16, V_w->fp16^T, zero g_score+c_v, g_gates/g_bias init, att_h^T
    convAB_kernel<<<(BSZ*TT*EP/4) / 256, 256>>>(enc, V_w, b_ih, b_hh, att_h,
                                                W_b, U_b, V_b, out);
    // K1: register-tiled conv + relu + maxpool -> featT (8 ch/block)
    conv_max_kernel<<<dim3(BSZ, NCH/CG), 256>>>(att_prev, conv_w);
    // K2: LSTM gates (transposed, k-split, atomic)
    gates_kernel<<<1024, 256>>>(W_ih, W_hh);
    // K3: fused LSTM elementwise + bias GEMV (h_new/c_new written by a-chunk 0)
    lstm_bias_kernel<<<dim3(4, BSZ, 4), 128>>>(att_c, dec_z, W_w, U_w, out);
    // K4: single-pass fp16 GEMM (f32 accum) + tanh/g-dot -> score
    score_mma_kernel<<<(BSZ*TT/128) * 4, 256, SCORE_SMEM>>>(g_w);
    // K5: masked scaled softmax -> w
    softmax_kernel<<<BSZ, 256>>>(enc_len, out);
    // K6: context vector (fp16 enc)
    context_kernel<<<dim3(2, 8, BSZ), 128>>>(out);
}

// round 13
// speedup vs baseline: 1.0806x; 1.0281x over previous
#include <cuda_runtime.h>
#include <cuda_fp16.h>
#include <cstdint>
#include <math.h>

#define BSZ 32
#define TT  2048
#define EP  512
#define AD  512
#define NCH 32
#define FILT 100
#define KW  201

// output layout: c_v (32*512), w (32*2048), h_new (32*512), c_new (32*512)
#define OUT_CV 0
#define OUT_W  (BSZ*EP)            // 16384
#define OUT_H  (OUT_W + BSZ*TT)    // 81920
#define OUT_C  (OUT_H + BSZ*AD)    // 98304

__device__ float g_featT[NCH*BSZ];         // [c][b]
__device__ float g_hT[AD*BSZ];             // att_h transposed [k][b]
__device__ float g_gates[BSZ*4*AD];
__device__ float g_bias[BSZ*AD];
__device__ float g_score[BSZ*TT];

// A = enc rounded to fp16, row-major (B*T, 512)
__device__ __half g_Ahalf[(size_t)BSZ*TT*EP];
// B = V_w^T rounded to fp16, n-major: (512 n-rows, 512 k-cols)
__device__ __half g_Bh[(size_t)AD*EP];

// ===========================================================================
// helpers
// ===========================================================================
__device__ __forceinline__ uint32_t smem_to_u32(const void* p) {
    uint32_t a;
    asm("{ .reg .u64 t; cvta.to.shared.u64 t, %1; cvt.u32.u64 %0, t; }" : "=r"(a) : "l"(p));
    return a;
}
__device__ __forceinline__ void cp_async16(uint32_t dst, const void* src) {
    asm volatile("cp.async.cg.shared.global [%0], [%1], 16;" :: "r"(dst), "l"(src));
}
__device__ __forceinline__ void cp_commit() {
    asm volatile("cp.async.commit_group;" ::: "memory");
}
__device__ __forceinline__ void ldsm4(uint32_t r[4], uint32_t addr) {
    asm volatile("ldmatrix.sync.aligned.m8n8.x4.shared.b16 {%0,%1,%2,%3}, [%4];"
        : "=r"(r[0]), "=r"(r[1]), "=r"(r[2]), "=r"(r[3]) : "r"(addr));
}
__device__ __forceinline__ void mma16816(float d[4], const uint32_t a[4],
                                         uint32_t b0, uint32_t b1) {
    asm volatile("mma.sync.aligned.m16n8k16.row.col.f32.f16.f16.f32 "
        "{%0,%1,%2,%3}, {%4,%5,%6,%7}, {%8,%9}, {%0,%1,%2,%3};"
        : "+f"(d[0]), "+f"(d[1]), "+f"(d[2]), "+f"(d[3])
        : "r"(a[0]), "r"(a[1]), "r"(a[2]), "r"(a[3]), "r"(b0), "r"(b1));
}

// FMA-only tanh: exp2 poly + bit-ldexp + magic-seed Newton reciprocal.
// abs err < ~1e-5; avoids MUFU (chip MUFU throughput is a wall at 33.5M calls).
__device__ __forceinline__ float fast_tanh(float x) {
    float ax = fminf(fabsf(x), 9.0f);
    float y = ax * 2.885390082f;                 // 2x * log2(e)
    float n = rintf(y);
    float f = y - n;
    float p = 1.3333558e-3f;
    p = fmaf(p, f, 9.6181291e-3f);
    p = fmaf(p, f, 5.5504109e-2f);
    p = fmaf(p, f, 2.4022651e-1f);
    p = fmaf(p, f, 6.9314718e-1f);
    p = fmaf(p, f, 1.0f);
    float z = __int_as_float(__float_as_int(p) + ((int)n << 23));   // e^{2ax}
    float d = z + 1.0f;
    float r = __int_as_float(0x7EF311C3u - __float_as_uint(d));     // ~1/d
    r = r * (2.0f - d * r);
    r = r * (2.0f - d * r);
    float t = (z - 1.0f) * r;
    return __int_as_float(__float_as_int(t) | (__float_as_int(x) & 0x80000000));
}

// ===========================================================================
// K0: enc -> fp16 (A); V_w -> fp16 transposed (B); zero g_score + c_v;
// g_gates = b_ih+b_hh; g_bias = W_b+U_b+V_b; att_h -> transposed. One launch.
// ===========================================================================
__global__ __launch_bounds__(256) void convAB_kernel(
    const float* __restrict__ enc, const float* __restrict__ Vw,
    const float* __restrict__ b_ih, const float* __restrict__ b_hh,
    const float* __restrict__ att_h, const float* __restrict__ W_b,
    const float* __restrict__ U_b, const float* __restrict__ V_b,
    float* __restrict__ out)
{
    int i4 = blockIdx.x * 256 + threadIdx.x;        // 8,388,608 threads
    if (i4 < BSZ*TT) g_score[i4] = 0.f;
    if (i4 < EP*AD) {
        int k = i4 >> 9, n = i4 & 511;
        g_Bh[(size_t)n*EP + k] = __float2half_rn(Vw[i4]);
    }
    if (i4 < BSZ*4*AD) {
        int j = i4 & (4*AD - 1);
        g_gates[i4] = b_ih[j] + b_hh[j];
    }
    if (i4 < AD*BSZ) {
        int k = i4 >> 5, b = i4 & 31;
        g_hT[i4] = att_h[b*AD + k];
    }
    if (i4 < BSZ*AD) {
        int a = i4 & 511;
        g_bias[i4] = W_b[a] + U_b[a] + V_b[a];   // bias atomics add on top
        out[OUT_CV + i4] = 0.f;                  // zero c_v for K6 atomics
    }
    size_t base = (size_t)i4 * 4;
    float4 v = *reinterpret_cast<const float4*>(enc + base);
    __half2 h01 = __floats2half2_rn(v.x, v.y);
    __half2 h23 = __floats2half2_rn(v.z, v.w);
    *reinterpret_cast<uint2*>(g_Ahalf + base) =
        make_uint2(*reinterpret_cast<uint32_t*>(&h01), *reinterpret_cast<uint32_t*>(&h23));
}

// ===========================================================================
// K1: location conv (201 taps) + relu + max-pool -> featT.
// Register-tiled FIR: thread owns 8 consecutive t; 8 channels per block.
// ===========================================================================
#define CG 8
#define XPAD (TT + 2*FILT + 8)     // 2256 floats, zero-padded
__global__ __launch_bounds__(256) void conv_max_kernel(
    const float* __restrict__ att_prev, const float* __restrict__ conv_w)
{
    int b = blockIdx.x, cg = blockIdx.y;
    __shared__ float xs[XPAD];
    __shared__ float ws[CG][KW + 1];
    __shared__ float red[CG * 8];
    int tid = threadIdx.x;
    for (int i = tid; i < XPAD; i += 256)
        xs[i] = (i >= FILT && i < FILT + TT) ? att_prev[b*TT + i - FILT] : 0.f;
    for (int i = tid; i < CG*KW; i += 256)
        ws[i / KW][i % KW] = conv_w[(cg*CG + i/KW)*KW + (i % KW)];
    __syncthreads();

    int t0 = tid * 8;
    float acc[CG][8];
    #pragma unroll
    for (int c = 0; c < CG; c++)
        #pragma unroll
        for (int i = 0; i < 8; i++) acc[c][i] = 0.f;

    for (int kb = 0; kb < 200; kb += 8) {
        float xw[16];
        const float4* xp = reinterpret_cast<const float4*>(xs + t0 + kb);
        *reinterpret_cast<float4*>(xw + 0)  = xp[0];
        *reinterpret_cast<float4*>(xw + 4)  = xp[1];
        *reinterpret_cast<float4*>(xw + 8)  = xp[2];
        *reinterpret_cast<float4*>(xw + 12) = xp[3];
        #pragma unroll
        for (int c = 0; c < CG; c++)
            #pragma unroll
            for (int j = 0; j < 8; j++) {
                float w = ws[c][kb + j];
                #pragma unroll
                for (int i = 0; i < 8; i++)
                    acc[c][i] = fmaf(w, xw[j + i], acc[c][i]);
            }
    }
    {   // k = 200
        float xw[8];
        const float4* xp = reinterpret_cast<const float4*>(xs + t0 + 200);
        *reinterpret_cast<float4*>(xw + 0) = xp[0];
        *reinterpret_cast<float4*>(xw + 4) = xp[1];
        #pragma unroll
        for (int c = 0; c < CG; c++) {
            float w = ws[c][200];
            #pragma unroll
            for (int i = 0; i < 8; i++)
                acc[c][i] = fmaf(w, xw[i], acc[c][i]);
        }
    }

    int lane = tid & 31, warp = tid >> 5;
    #pragma unroll
    for (int c = 0; c < CG; c++) {
        float m = 0.f;
        #pragma unroll
        for (int i = 0; i < 8; i++) m = fmaxf(m, acc[c][i]);
        #pragma unroll
        for (int o = 16; o > 0; o >>= 1)
            m = fmaxf(m, __shfl_xor_sync(0xffffffffu, m, o));
        if (lane == 0) red[c*8 + warp] = m;
    }
    __syncthreads();
    if (tid < CG) {
        float m = red[tid*8];
        #pragma unroll
        for (int wp = 1; wp < 8; wp++) m = fmaxf(m, red[tid*8 + wp]);
        g_featT[(cg*CG + tid)*BSZ + b] = m;
    }
}

// ===========================================================================
// K2: LSTM gates, transposed-operand form: warp = (j, ks), lanes = b.
// ===========================================================================
__global__ __launch_bounds__(256) void gates_kernel(
    const float* __restrict__ W_ih, const float* __restrict__ W_hh)
{
    int w = blockIdx.x * 8 + (threadIdx.x >> 5);
    int lane = threadIdx.x & 31;        // = b
    int j = w >> 2, ks = w & 3;
    const float4* wr = reinterpret_cast<const float4*>(W_hh + (size_t)j*AD + ks*128);
    const float* ht = g_hT + ks*128*BSZ + lane;
    float s0 = 0.f, s1 = 0.f, s2 = 0.f, s3 = 0.f;
    #pragma unroll
    for (int k = 0; k < 32; k++) {
        float4 wv = __ldg(wr + k);
        s0 = fmaf(wv.x, ht[(4*k+0)*BSZ], s0);
        s1 = fmaf(wv.y, ht[(4*k+1)*BSZ], s1);
        s2 = fmaf(wv.z, ht[(4*k+2)*BSZ], s2);
        s3 = fmaf(wv.w, ht[(4*k+3)*BSZ], s3);
    }
    float s = s0 + s1 + s2 + s3;
    if (ks == 0) {
        const float* wi = W_ih + j*NCH;
        #pragma unroll
        for (int c = 0; c < NCH; c++)
            s = fmaf(__ldg(wi + c), g_featT[c*BSZ + lane], s);
    }
    atomicAdd(&g_gates[lane*4*AD + j], s);
}

// ===========================================================================
// K3: fused LSTM + bias, weight-stationary. grid (4 a-chunks, 16 k-chunks, 2
// b-groups), block 128. W_w/U_w column slices (32 k each) live in registers;
// block computes lstm for its (16 b x 32 k) into smem then loops b with
// reg-resident FMAs. W/U read exactly once chip-wide (2 MB, no redundancy).
// ===========================================================================
__global__ __launch_bounds__(128) void lstm_bias_kernel(
    const float* __restrict__ att_c, const float* __restrict__ dec_z,
    const float* __restrict__ W_w, const float* __restrict__ U_w,
    float* __restrict__ out)
{
    int a  = blockIdx.x * 128 + threadIdx.x;
    int k0 = blockIdx.y * 32;
    int b0 = blockIdx.z * 16;
    __shared__ float hs[16][33], zs[16][33];

    // weight slices into registers (64 coalesced LDG, high MLP)
    float wv[32], uv[32];
    #pragma unroll
    for (int k = 0; k < 32; k++) {
        wv[k] = __ldg(W_w + (size_t)(k0 + k)*AD + a);
        uv[k] = __ldg(U_w + (size_t)(k0 + k)*AD + a);
    }

    // lstm for (16 b x 32 k): 512 evals, 4 per thread
    #pragma unroll
    for (int it = 0; it < 4; it++) {
        int u = threadIdx.x + it*128;
        int bl = u >> 5, k = u & 31;
        int b = b0 + bl;
        int idx = b*AD + k0 + k;
        const float* g = g_gates + b*4*AD + k0 + k;
        float gi = g[0], gf = g[AD], gg = g[2*AD], go = g[3*AD];
        float si = 1.f / (1.f + expf(-gi));
        float sf = 1.f / (1.f + expf(-gf));
        float so = 1.f / (1.f + expf(-go));
        float cn = sf * att_c[idx] + si * tanhf(gg);
        float hn = so * tanhf(cn);
        hs[bl][k] = hn;
        zs[bl][k] = dec_z[idx];
        if (blockIdx.x == 0) {
            out[OUT_H + idx] = hn;
            out[OUT_C + idx] = cn;
        }
    }
    __syncthreads();

    // b-loop: reg-resident weights x smem-broadcast activations
    #pragma unroll 2
    for (int bl = 0; bl < 16; bl++) {
        float s0 = 0.f, s1 = 0.f;
        #pragma unroll
        for (int k = 0; k < 32; k += 2) {
            s0 = fmaf(wv[k],   hs[bl][k],   s0);
            s0 = fmaf(uv[k],   zs[bl][k],   s0);
            s1 = fmaf(wv[k+1], hs[bl][k+1], s1);
            s1 = fmaf(uv[k+1], zs[bl][k+1], s1);
        }
        atomicAdd(&g_bias[(b0 + bl)*AD + a], s0 + s1);
    }
}

// ===========================================================================
// K4: mma.sync fp16 score GEMM + fused tanh/g-dot epilogue (512-CTA launch —
// persistent variant measured slower, R11). CTA tile 128x128; BK=64 chunks
// double-buffered via cp.async. 8 warps 2(M)x4(N).
// ===========================================================================
#define ASTR 72                      // fp16 elems per smem row (144B: conflict-free ldmatrix)
#define CHUNK_B (128*ASTR*2)         // 18432 bytes per 128x64 chunk
#define SCORE_SMEM (4*CHUNK_B)       // 2 stages x {A,B} = 73728 B

__device__ __forceinline__ void compute_chunk(
    uint32_t aBase, uint32_t bBase, int warp_m, int warp_n, int lane,
    float (&acc)[4][4][4])
{
    int rsel = lane & 15, csel = (lane >> 4) * 8;
    #pragma unroll
    for (int ks = 0; ks < 4; ks++) {
        uint32_t a[4][4], bq[2][4];
        #pragma unroll
        for (int mt = 0; mt < 4; mt++) {
            uint32_t addr = aBase + ((warp_m*64 + mt*16 + rsel)*ASTR + csel + ks*16)*2;
            ldsm4(a[mt], addr);
        }
        #pragma unroll
        for (int np = 0; np < 2; np++) {
            uint32_t addr = bBase + ((warp_n*32 + np*16 + rsel)*ASTR + csel + ks*16)*2;
            ldsm4(bq[np], addr);
        }
        #pragma unroll
        for (int mt = 0; mt < 4; mt++)
            #pragma unroll
            for (int nt = 0; nt < 4; nt++)
                mma16816(acc[mt][nt], a[mt], bq[nt>>1][nt&1], bq[nt>>1][2+(nt&1)]);
    }
}

__global__ __launch_bounds__(256, 2) void score_mma_kernel(const float* __restrict__ gw)
{
    extern __shared__ char smem[];
    uint32_t smem_base = smem_to_u32(smem);
    int tid = threadIdx.x, lane = tid & 31, wid = tid >> 5;
    int mtile = blockIdx.x >> 2, ntile = blockIdx.x & 3;   // adjacent n-tiles: A reuse in L2
    int row0 = mtile * 128, n0 = ntile * 128;
    int b = row0 / TT;
    int warp_m = wid & 1, warp_n = wid >> 1;

    float acc[4][4][4];
    #pragma unroll
    for (int mt = 0; mt < 4; mt++)
        #pragma unroll
        for (int nt = 0; nt < 4; nt++)
            #pragma unroll
            for (int i = 0; i < 4; i++) acc[mt][nt][i] = 0.f;

    const __half* Arow = g_Ahalf + (size_t)row0 * EP;
    const __half* Brow = g_Bh + (size_t)n0 * EP;

    auto load_set = [&](int s, int kc) {
        uint32_t ah = smem_base + (uint32_t)(s*2 + 0) * CHUNK_B;
        uint32_t bh = smem_base + (uint32_t)(s*2 + 1) * CHUNK_B;
        const __half* Aq = Arow + kc*64;
        const __half* Bq = Brow + kc*64;
        #pragma unroll
        for (int j = 0; j < 4; j++) {
            int p = tid + 256*j;
            int r = p >> 3, q = p & 7;
            cp_async16(ah + (r*ASTR + q*8)*2, Aq + (size_t)r*EP + q*8);
            cp_async16(bh + (r*ASTR + q*8)*2, Bq + (size_t)r*EP + q*8);
        }
        cp_commit();
    };

    load_set(0, 0);
    for (int kc = 0; kc < 8; kc++) {
        if (kc + 1 < 8) {
            load_set((kc + 1) & 1, kc + 1);
            asm volatile("cp.async.wait_group 1;" ::: "memory");
        } else {
            asm volatile("cp.async.wait_group 0;" ::: "memory");
        }
        __syncthreads();
        int s = kc & 1;
        uint32_t Ah = smem_base + (uint32_t)(s*2 + 0) * CHUNK_B;
        uint32_t Bh = smem_base + (uint32_t)(s*2 + 1) * CHUNK_B;
        compute_chunk(Ah, Bh, warp_m, warp_n, lane, acc);
        __syncthreads();
    }

    // epilogue: rowsum += g[n]*tanh(acc + bias[b,n]); reduce 4 q-lanes; atomic
    int gq = lane >> 2, q = lane & 3;
    float gv[8], bb[8];
    #pragma unroll
    for (int nt = 0; nt < 4; nt++)
        #pragma unroll
        for (int h = 0; h < 2; h++) {
            int n = n0 + warp_n*32 + nt*8 + q*2 + h;
            gv[nt*2 + h] = __ldg(gw + n);
            bb[nt*2 + h] = g_bias[b*AD + n];
        }
    #pragma unroll
    for (int mt = 0; mt < 4; mt++) {
        float p0 = 0.f, p1 = 0.f;
        #pragma unroll
        for (int nt = 0; nt < 4; nt++) {
            p0 += gv[nt*2+0] * fast_tanh(acc[mt][nt][0] + bb[nt*2+0]);
            p0 += gv[nt*2+1] * fast_tanh(acc[mt][nt][1] + bb[nt*2+1]);
            p1 += gv[nt*2+0] * fast_tanh(acc[mt][nt][2] + bb[nt*2+0]);
            p1 += gv[nt*2+1] * fast_tanh(acc[mt][nt][3] + bb[nt*2+1]);
        }
        p0 += __shfl_xor_sync(0xffffffffu, p0, 1);
        p0 += __shfl_xor_sync(0xffffffffu, p0, 2);
        p1 += __shfl_xor_sync(0xffffffffu, p1, 1);
        p1 += __shfl_xor_sync(0xffffffffu, p1, 2);
        if (q == 0) {
            atomicAdd(&g_score[row0 + warp_m*64 + mt*16 + gq],     p0);
            atomicAdd(&g_score[row0 + warp_m*64 + mt*16 + 8 + gq], p1);
        }
    }
}

// ===========================================================================
// K5: masked, scaled softmax over T per batch -> w (g_b dropped: shift-invariant)
// ===========================================================================
__global__ __launch_bounds__(256) void softmax_kernel(
    const int* __restrict__ len, float* __restrict__ out)
{
    int b = blockIdx.x;
    int L = len[b];
    __shared__ float red[256];
    float* wout = out + OUT_W + b*TT;

    float mx = -3.0e38f;
    for (int t = threadIdx.x; t < TT; t += 256) {
        float v = (t < L) ? 2.0f * g_score[b*TT + t] : -3.0e38f;
        mx = fmaxf(mx, v);
    }
    red[threadIdx.x] = mx; __syncthreads();
    for (int s = 128; s > 0; s >>= 1) {
        if (threadIdx.x < s) red[threadIdx.x] = fmaxf(red[threadIdx.x], red[threadIdx.x + s]);
        __syncthreads();
    }
    mx = red[0]; __syncthreads();

    float sum = 0.f;
    for (int t = threadIdx.x; t < TT; t += 256) {
        float p = (t < L) ? expf(2.0f * g_score[b*TT + t] - mx) : 0.f;
        wout[t] = p;
        sum += p;
    }
    red[threadIdx.x] = sum; __syncthreads();
    for (int s = 128; s > 0; s >>= 1) {
        if (threadIdx.x < s) red[threadIdx.x] += red[threadIdx.x + s];
        __syncthreads();
    }
    float inv = 1.0f / red[0];
    for (int t = threadIdx.x; t < TT; t += 256) wout[t] *= inv;
}

// ===========================================================================
// K6: context c_v[b,e] = sum_t w[b,t]*enc16[b,t,e]  (fp16 enc: half traffic)
// ===========================================================================
__global__ __launch_bounds__(128) void context_kernel(float* __restrict__ out)
{
    int b = blockIdx.z;
    int e0 = blockIdx.x * 256 + threadIdx.x * 2;
    int t0 = blockIdx.y * 256;
    const float* wrow = out + OUT_W + b*TT + t0;
    const __half* ep = g_Ahalf + ((size_t)b*TT + t0)*EP + e0;
    float s0 = 0.f, s1 = 0.f;
    #pragma unroll 8
    for (int t = 0; t < 256; t++) {
        float wv = __ldg(wrow + t);
        __half2 h = *reinterpret_cast<const __half2*>(ep + (size_t)t*EP);
        float2 v = __half22float2(h);
        s0 = fmaf(wv, v.x, s0);
        s1 = fmaf(wv, v.y, s1);
    }
    atomicAdd(&out[OUT_CV + b*EP + e0],     s0);
    atomicAdd(&out[OUT_CV + b*EP + e0 + 1], s1);
}

// ===========================================================================
extern "C" void kernel_launch(void* const* d_in, const int* in_sizes, int n_in,
                              void* d_out, int out_size)
{
    const float* enc      = (const float*)d_in[0];
    const int*   enc_len  = (const int*)  d_in[1];
    const float* dec_z    = (const float*)d_in[2];
    const float* att_prev = (const float*)d_in[3];
    const float* att_h    = (const float*)d_in[4];
    const float* att_c    = (const float*)d_in[5];
    const float* W_w      = (const float*)d_in[6];
    const float* W_b      = (const float*)d_in[7];
    const float* V_w      = (const float*)d_in[8];
    const float* V_b      = (const float*)d_in[9];
    const float* U_w      = (const float*)d_in[10];
    const float* U_b      = (const float*)d_in[11];
    const float* g_w      = (const float*)d_in[12];
    const float* g_b      = (const float*)d_in[13];  // unused: softmax shift-invariant
    const float* conv_w   = (const float*)d_in[14];
    const float* W_ih     = (const float*)d_in[15];
    const float* W_hh     = (const float*)d_in[16];
    const float* b_ih     = (const float*)d_in[17];
    const float* b_hh     = (const float*)d_in[18];
    float* out = (float*)d_out;
    (void)g_b;

    cudaFuncSetAttribute(score_mma_kernel, cudaFuncAttributeMaxDynamicSharedMemorySize, SCORE_SMEM);

    // K0: enc->fp16, V_w->fp16^T, zero g_score+c_v, g_gates/g_bias init, att_h^T
    convAB_kernel<<<(BSZ*TT*EP/4) / 256, 256>>>(enc, V_w, b_ih, b_hh, att_h,
                                                W_b, U_b, V_b, out);
    // K1: register-tiled conv + relu + maxpool -> featT (8 ch/block)
    conv_max_kernel<<<dim3(BSZ, NCH/CG), 256>>>(att_prev, conv_w);
    // K2: LSTM gates (transposed, k-split, atomic)
    gates_kernel<<<1024, 256>>>(W_ih, W_hh);
    // K3: fused LSTM + bias, weight-stationary (h_new/c_new by a-chunk 0)
    lstm_bias_kernel<<<dim3(4, 16, 2), 128>>>(att_c, dec_z, W_w, U_w, out);
    // K4: single-pass fp16 GEMM (f32 accum) + tanh/g-dot -> score
    score_mma_kernel<<<(BSZ*TT/128) * 4, 256, SCORE_SMEM>>>(g_w);
    // K5: masked scaled softmax -> w
    softmax_kernel<<<BSZ, 256>>>(enc_len, out);
    // K6: context vector (fp16 enc)
    context_kernel<<<dim3(2, 8, BSZ), 128>>>(out);
}

// round 14
// speedup vs baseline: 1.1124x; 1.0294x over previous
#include <cuda_runtime.h>
#include <cuda_fp16.h>
#include <cstdint>
#include <math.h>

#define BSZ 32
#define TT  2048
#define EP  512
#define AD  512
#define NCH 32
#define FILT 100
#define KW  201

// output layout: c_v (32*512), w (32*2048), h_new (32*512), c_new (32*512)
#define OUT_CV 0
#define OUT_W  (BSZ*EP)            // 16384
#define OUT_H  (OUT_W + BSZ*TT)    // 81920
#define OUT_C  (OUT_H + BSZ*AD)    // 98304

__device__ float g_featT[NCH*BSZ];         // [c][b]
__device__ float g_hT[AD*BSZ];             // att_h transposed [k][b]
__device__ float g_gates[BSZ*4*AD];
__device__ float g_bias[BSZ*AD];
__device__ float g_score[BSZ*TT];

// A = enc rounded to fp16, row-major (B*T, 512)
__device__ __half g_Ahalf[(size_t)BSZ*TT*EP];
// B = V_w^T rounded to fp16, n-major: (512 n-rows, 512 k-cols)
__device__ __half g_Bh[(size_t)AD*EP];

// ===========================================================================
// helpers
// ===========================================================================
__device__ __forceinline__ uint32_t smem_to_u32(const void* p) {
    uint32_t a;
    asm("{ .reg .u64 t; cvta.to.shared.u64 t, %1; cvt.u32.u64 %0, t; }" : "=r"(a) : "l"(p));
    return a;
}
__device__ __forceinline__ void cp_async16(uint32_t dst, const void* src) {
    asm volatile("cp.async.cg.shared.global [%0], [%1], 16;" :: "r"(dst), "l"(src));
}
__device__ __forceinline__ void cp_commit() {
    asm volatile("cp.async.commit_group;" ::: "memory");
}
__device__ __forceinline__ void ldsm4(uint32_t r[4], uint32_t addr) {
    asm volatile("ldmatrix.sync.aligned.m8n8.x4.shared.b16 {%0,%1,%2,%3}, [%4];"
        : "=r"(r[0]), "=r"(r[1]), "=r"(r[2]), "=r"(r[3]) : "r"(addr));
}
__device__ __forceinline__ void mma16816(float d[4], const uint32_t a[4],
                                         uint32_t b0, uint32_t b1) {
    asm volatile("mma.sync.aligned.m16n8k16.row.col.f32.f16.f16.f32 "
        "{%0,%1,%2,%3}, {%4,%5,%6,%7}, {%8,%9}, {%0,%1,%2,%3};"
        : "+f"(d[0]), "+f"(d[1]), "+f"(d[2]), "+f"(d[3])
        : "r"(a[0]), "r"(a[1]), "r"(a[2]), "r"(a[3]), "r"(b0), "r"(b1));
}

// FMA-only tanh: exp2 poly + bit-ldexp + magic-seed Newton reciprocal.
// abs err < ~1e-5; avoids MUFU (chip MUFU throughput is a wall at 33.5M calls).
__device__ __forceinline__ float fast_tanh(float x) {
    float ax = fminf(fabsf(x), 9.0f);
    float y = ax * 2.885390082f;                 // 2x * log2(e)
    float n = rintf(y);
    float f = y - n;
    float p = 1.3333558e-3f;
    p = fmaf(p, f, 9.6181291e-3f);
    p = fmaf(p, f, 5.5504109e-2f);
    p = fmaf(p, f, 2.4022651e-1f);
    p = fmaf(p, f, 6.9314718e-1f);
    p = fmaf(p, f, 1.0f);
    float z = __int_as_float(__float_as_int(p) + ((int)n << 23));   // e^{2ax}
    float d = z + 1.0f;
    float r = __int_as_float(0x7EF311C3u - __float_as_uint(d));     // ~1/d
    r = r * (2.0f - d * r);
    r = r * (2.0f - d * r);
    float t = (z - 1.0f) * r;
    return __int_as_float(__float_as_int(t) | (__float_as_int(x) & 0x80000000));
}

// ===========================================================================
// K0: enc -> fp16 (A); V_w -> fp16 transposed (B); zero g_score + c_v;
// g_gates = b_ih+b_hh; g_bias = W_b+U_b+V_b; att_h -> transposed. One launch.
// ===========================================================================
__global__ __launch_bounds__(256) void convAB_kernel(
    const float* __restrict__ enc, const float* __restrict__ Vw,
    const float* __restrict__ b_ih, const float* __restrict__ b_hh,
    const float* __restrict__ att_h, const float* __restrict__ W_b,
    const float* __restrict__ U_b, const float* __restrict__ V_b,
    float* __restrict__ out)
{
    int i4 = blockIdx.x * 256 + threadIdx.x;        // 8,388,608 threads
    if (i4 < BSZ*TT) g_score[i4] = 0.f;
    if (i4 < EP*AD) {
        int k = i4 >> 9, n = i4 & 511;
        g_Bh[(size_t)n*EP + k] = __float2half_rn(Vw[i4]);
    }
    if (i4 < BSZ*4*AD) {
        int j = i4 & (4*AD - 1);
        g_gates[i4] = b_ih[j] + b_hh[j];
    }
    if (i4 < AD*BSZ) {
        int k = i4 >> 5, b = i4 & 31;
        g_hT[i4] = att_h[b*AD + k];
    }
    if (i4 < BSZ*AD) {
        int a = i4 & 511;
        g_bias[i4] = W_b[a] + U_b[a] + V_b[a];   // bias atomics add on top
        out[OUT_CV + i4] = 0.f;                  // zero c_v for K6 atomics
    }
    size_t base = (size_t)i4 * 4;
    float4 v = *reinterpret_cast<const float4*>(enc + base);
    __half2 h01 = __floats2half2_rn(v.x, v.y);
    __half2 h23 = __floats2half2_rn(v.z, v.w);
    *reinterpret_cast<uint2*>(g_Ahalf + base) =
        make_uint2(*reinterpret_cast<uint32_t*>(&h01), *reinterpret_cast<uint32_t*>(&h23));
}

// ===========================================================================
// K1: location conv (201 taps) + relu + max-pool -> featT.
// Register-tiled FIR: thread owns 8 consecutive t; 4 channels per block
// (CG=4: 2x blocks vs R13 -> better latency hiding; acc regs halve).
// ===========================================================================
#define CG 4
#define XPAD (TT + 2*FILT + 8)     // 2256 floats, zero-padded
__global__ __launch_bounds__(256) void conv_max_kernel(
    const float* __restrict__ att_prev, const float* __restrict__ conv_w)
{
    int b = blockIdx.x, cg = blockIdx.y;
    __shared__ float xs[XPAD];
    __shared__ float ws[CG][KW + 1];
    __shared__ float red[CG * 8];
    int tid = threadIdx.x;
    for (int i = tid; i < XPAD; i += 256)
        xs[i] = (i >= FILT && i < FILT + TT) ? att_prev[b*TT + i - FILT] : 0.f;
    for (int i = tid; i < CG*KW; i += 256)
        ws[i / KW][i % KW] = conv_w[(cg*CG + i/KW)*KW + (i % KW)];
    __syncthreads();

    int t0 = tid * 8;
    float acc[CG][8];
    #pragma unroll
    for (int c = 0; c < CG; c++)
        #pragma unroll
        for (int i = 0; i < 8; i++) acc[c][i] = 0.f;

    for (int kb = 0; kb < 200; kb += 8) {
        float xw[16];
        const float4* xp = reinterpret_cast<const float4*>(xs + t0 + kb);
        *reinterpret_cast<float4*>(xw + 0)  = xp[0];
        *reinterpret_cast<float4*>(xw + 4)  = xp[1];
        *reinterpret_cast<float4*>(xw + 8)  = xp[2];
        *reinterpret_cast<float4*>(xw + 12) = xp[3];
        #pragma unroll
        for (int c = 0; c < CG; c++)
            #pragma unroll
            for (int j = 0; j < 8; j++) {
                float w = ws[c][kb + j];
                #pragma unroll
                for (int i = 0; i < 8; i++)
                    acc[c][i] = fmaf(w, xw[j + i], acc[c][i]);
            }
    }
    {   // k = 200
        float xw[8];
        const float4* xp = reinterpret_cast<const float4*>(xs + t0 + 200);
        *reinterpret_cast<float4*>(xw + 0) = xp[0];
        *reinterpret_cast<float4*>(xw + 4) = xp[1];
        #pragma unroll
        for (int c = 0; c < CG; c++) {
            float w = ws[c][200];
            #pragma unroll
            for (int i = 0; i < 8; i++)
                acc[c][i] = fmaf(w, xw[i], acc[c][i]);
        }
    }

    int lane = tid & 31, warp = tid >> 5;
    #pragma unroll
    for (int c = 0; c < CG; c++) {
        float m = 0.f;
        #pragma unroll
        for (int i = 0; i < 8; i++) m = fmaxf(m, acc[c][i]);
        #pragma unroll
        for (int o = 16; o > 0; o >>= 1)
            m = fmaxf(m, __shfl_xor_sync(0xffffffffu, m, o));
        if (lane == 0) red[c*8 + warp] = m;
    }
    __syncthreads();
    if (tid < CG) {
        float m = red[tid*8];
        #pragma unroll
        for (int wp = 1; wp < 8; wp++) m = fmaxf(m, red[tid*8 + wp]);
        g_featT[(cg*CG + tid)*BSZ + b] = m;
    }
}

// ===========================================================================
// K2: LSTM gates, transposed-operand form: warp = (j, ks), lanes = b.
// ===========================================================================
__global__ __launch_bounds__(256) void gates_kernel(
    const float* __restrict__ W_ih, const float* __restrict__ W_hh)
{
    int w = blockIdx.x * 8 + (threadIdx.x >> 5);
    int lane = threadIdx.x & 31;        // = b
    int j = w >> 2, ks = w & 3;
    const float4* wr = reinterpret_cast<const float4*>(W_hh + (size_t)j*AD + ks*128);
    const float* ht = g_hT + ks*128*BSZ + lane;
    float s0 = 0.f, s1 = 0.f, s2 = 0.f, s3 = 0.f;
    #pragma unroll
    for (int k = 0; k < 32; k++) {
        float4 wv = __ldg(wr + k);
        s0 = fmaf(wv.x, ht[(4*k+0)*BSZ], s0);
        s1 = fmaf(wv.y, ht[(4*k+1)*BSZ], s1);
        s2 = fmaf(wv.z, ht[(4*k+2)*BSZ], s2);
        s3 = fmaf(wv.w, ht[(4*k+3)*BSZ], s3);
    }
    float s = s0 + s1 + s2 + s3;
    if (ks == 0) {
        const float* wi = W_ih + j*NCH;
        #pragma unroll
        for (int c = 0; c < NCH; c++)
            s = fmaf(__ldg(wi + c), g_featT[c*BSZ + lane], s);
    }
    atomicAdd(&g_gates[lane*4*AD + j], s);
}

// ===========================================================================
// K3: fused LSTM + bias, weight-stationary. grid (4 a-chunks, 16 k-chunks, 4
// b-groups of 8), block 128 -> 256 blocks (2x R13: latency hiding).
// W_w/U_w column slices (32 k each) in registers; lstm into smem; b-loop.
// ===========================================================================
#define BG 8
__global__ __launch_bounds__(128) void lstm_bias_kernel(
    const float* __restrict__ att_c, const float* __restrict__ dec_z,
    const float* __restrict__ W_w, const float* __restrict__ U_w,
    float* __restrict__ out)
{
    int a  = blockIdx.x * 128 + threadIdx.x;
    int k0 = blockIdx.y * 32;
    int b0 = blockIdx.z * BG;
    __shared__ float hs[BG][33], zs[BG][33];

    // weight slices into registers (64 coalesced LDG, high MLP)
    float wv[32], uv[32];
    #pragma unroll
    for (int k = 0; k < 32; k++) {
        wv[k] = __ldg(W_w + (size_t)(k0 + k)*AD + a);
        uv[k] = __ldg(U_w + (size_t)(k0 + k)*AD + a);
    }

    // lstm for (BG b x 32 k): 256 evals, 2 per thread
    #pragma unroll
    for (int it = 0; it < 2; it++) {
        int u = threadIdx.x + it*128;
        int bl = u >> 5, k = u & 31;
        int b = b0 + bl;
        int idx = b*AD + k0 + k;
        const float* g = g_gates + b*4*AD + k0 + k;
        float gi = g[0], gf = g[AD], gg = g[2*AD], go = g[3*AD];
        float si = 1.f / (1.f + expf(-gi));
        float sf = 1.f / (1.f + expf(-gf));
        float so = 1.f / (1.f + expf(-go));
        float cn = sf * att_c[idx] + si * tanhf(gg);
        float hn = so * tanhf(cn);
        hs[bl][k] = hn;
        zs[bl][k] = dec_z[idx];
        if (blockIdx.x == 0) {
            out[OUT_H + idx] = hn;
            out[OUT_C + idx] = cn;
        }
    }
    __syncthreads();

    // b-loop: reg-resident weights x smem-broadcast activations
    #pragma unroll 2
    for (int bl = 0; bl < BG; bl++) {
        float s0 = 0.f, s1 = 0.f;
        #pragma unroll
        for (int k = 0; k < 32; k += 2) {
            s0 = fmaf(wv[k],   hs[bl][k],   s0);
            s0 = fmaf(uv[k],   zs[bl][k],   s0);
            s1 = fmaf(wv[k+1], hs[bl][k+1], s1);
            s1 = fmaf(uv[k+1], zs[bl][k+1], s1);
        }
        atomicAdd(&g_bias[(b0 + bl)*AD + a], s0 + s1);
    }
}

// ===========================================================================
// K4: mma.sync fp16 score GEMM + fused tanh/g-dot epilogue (512-CTA launch —
// persistent variant measured slower, R11). CTA tile 128x128; BK=64 chunks
// double-buffered via cp.async. 8 warps 2(M)x4(N). At fallback-HMMA ceiling.
// ===========================================================================
#define ASTR 72                      // fp16 elems per smem row (144B: conflict-free ldmatrix)
#define CHUNK_B (128*ASTR*2)         // 18432 bytes per 128x64 chunk
#define SCORE_SMEM (4*CHUNK_B)       // 2 stages x {A,B} = 73728 B

__device__ __forceinline__ void compute_chunk(
    uint32_t aBase, uint32_t bBase, int warp_m, int warp_n, int lane,
    float (&acc)[4][4][4])
{
    int rsel = lane & 15, csel = (lane >> 4) * 8;
    #pragma unroll
    for (int ks = 0; ks < 4; ks++) {
        uint32_t a[4][4], bq[2][4];
        #pragma unroll
        for (int mt = 0; mt < 4; mt++) {
            uint32_t addr = aBase + ((warp_m*64 + mt*16 + rsel)*ASTR + csel + ks*16)*2;
            ldsm4(a[mt], addr);
        }
        #pragma unroll
        for (int np = 0; np < 2; np++) {
            uint32_t addr = bBase + ((warp_n*32 + np*16 + rsel)*ASTR + csel + ks*16)*2;
            ldsm4(bq[np], addr);
        }
        #pragma unroll
        for (int mt = 0; mt < 4; mt++)
            #pragma unroll
            for (int nt = 0; nt < 4; nt++)
                mma16816(acc[mt][nt], a[mt], bq[nt>>1][nt&1], bq[nt>>1][2+(nt&1)]);
    }
}

__global__ __launch_bounds__(256, 2) void score_mma_kernel(const float* __restrict__ gw)
{
    extern __shared__ char smem[];
    uint32_t smem_base = smem_to_u32(smem);
    int tid = threadIdx.x, lane = tid & 31, wid = tid >> 5;
    int mtile = blockIdx.x >> 2, ntile = blockIdx.x & 3;   // adjacent n-tiles: A reuse in L2
    int row0 = mtile * 128, n0 = ntile * 128;
    int b = row0 / TT;
    int warp_m = wid & 1, warp_n = wid >> 1;

    float acc[4][4][4];
    #pragma unroll
    for (int mt = 0; mt < 4; mt++)
        #pragma unroll
        for (int nt = 0; nt < 4; nt++)
            #pragma unroll
            for (int i = 0; i < 4; i++) acc[mt][nt][i] = 0.f;

    const __half* Arow = g_Ahalf + (size_t)row0 * EP;
    const __half* Brow = g_Bh + (size_t)n0 * EP;

    auto load_set = [&](int s, int kc) {
        uint32_t ah = smem_base + (uint32_t)(s*2 + 0) * CHUNK_B;
        uint32_t bh = smem_base + (uint32_t)(s*2 + 1) * CHUNK_B;
        const __half* Aq = Arow + kc*64;
        const __half* Bq = Brow + kc*64;
        #pragma unroll
        for (int j = 0; j < 4; j++) {
            int p = tid + 256*j;
            int r = p >> 3, q = p & 7;
            cp_async16(ah + (r*ASTR + q*8)*2, Aq + (size_t)r*EP + q*8);
            cp_async16(bh + (r*ASTR + q*8)*2, Bq + (size_t)r*EP + q*8);
        }
        cp_commit();
    };

    load_set(0, 0);
    for (int kc = 0; kc < 8; kc++) {
        if (kc + 1 < 8) {
            load_set((kc + 1) & 1, kc + 1);
            asm volatile("cp.async.wait_group 1;" ::: "memory");
        } else {
            asm volatile("cp.async.wait_group 0;" ::: "memory");
        }
        __syncthreads();
        int s = kc & 1;
        uint32_t Ah = smem_base + (uint32_t)(s*2 + 0) * CHUNK_B;
        uint32_t Bh = smem_base + (uint32_t)(s*2 + 1) * CHUNK_B;
        compute_chunk(Ah, Bh, warp_m, warp_n, lane, acc);
        __syncthreads();
    }

    // epilogue: rowsum += g[n]*tanh(acc + bias[b,n]); reduce 4 q-lanes; atomic
    int gq = lane >> 2, q = lane & 3;
    float gv[8], bb[8];
    #pragma unroll
    for (int nt = 0; nt < 4; nt++)
        #pragma unroll
        for (int h = 0; h < 2; h++) {
            int n = n0 + warp_n*32 + nt*8 + q*2 + h;
            gv[nt*2 + h] = __ldg(gw + n);
            bb[nt*2 + h] = g_bias[b*AD + n];
        }
    #pragma unroll
    for (int mt = 0; mt < 4; mt++) {
        float p0 = 0.f, p1 = 0.f;
        #pragma unroll
        for (int nt = 0; nt < 4; nt++) {
            p0 += gv[nt*2+0] * fast_tanh(acc[mt][nt][0] + bb[nt*2+0]);
            p0 += gv[nt*2+1] * fast_tanh(acc[mt][nt][1] + bb[nt*2+1]);
            p1 += gv[nt*2+0] * fast_tanh(acc[mt][nt][2] + bb[nt*2+0]);
            p1 += gv[nt*2+1] * fast_tanh(acc[mt][nt][3] + bb[nt*2+1]);
        }
        p0 += __shfl_xor_sync(0xffffffffu, p0, 1);
        p0 += __shfl_xor_sync(0xffffffffu, p0, 2);
        p1 += __shfl_xor_sync(0xffffffffu, p1, 1);
        p1 += __shfl_xor_sync(0xffffffffu, p1, 2);
        if (q == 0) {
            atomicAdd(&g_score[row0 + warp_m*64 + mt*16 + gq],     p0);
            atomicAdd(&g_score[row0 + warp_m*64 + mt*16 + 8 + gq], p1);
        }
    }
}

// ===========================================================================
// K5: masked, scaled softmax over T per batch -> w (g_b dropped: shift-invariant)
// ===========================================================================
__global__ __launch_bounds__(256) void softmax_kernel(
    const int* __restrict__ len, float* __restrict__ out)
{
    int b = blockIdx.x;
    int L = len[b];
    __shared__ float red[256];
    float* wout = out + OUT_W + b*TT;

    float mx = -3.0e38f;
    for (int t = threadIdx.x; t < TT; t += 256) {
        float v = (t < L) ? 2.0f * g_score[b*TT + t] : -3.0e38f;
        mx = fmaxf(mx, v);
    }
    red[threadIdx.x] = mx; __syncthreads();
    for (int s = 128; s > 0; s >>= 1) {
        if (threadIdx.x < s) red[threadIdx.x] = fmaxf(red[threadIdx.x], red[threadIdx.x + s]);
        __syncthreads();
    }
    mx = red[0]; __syncthreads();

    float sum = 0.f;
    for (int t = threadIdx.x; t < TT; t += 256) {
        float p = (t < L) ? expf(2.0f * g_score[b*TT + t] - mx) : 0.f;
        wout[t] = p;
        sum += p;
    }
    red[threadIdx.x] = sum; __syncthreads();
    for (int s = 128; s > 0; s >>= 1) {
        if (threadIdx.x < s) red[threadIdx.x] += red[threadIdx.x + s];
        __syncthreads();
    }
    float inv = 1.0f / red[0];
    for (int t = threadIdx.x; t < TT; t += 256) wout[t] *= inv;
}

// ===========================================================================
// K6: context c_v[b,e] = sum_t w[b,t]*enc16[b,t,e]  (fp16 enc: half traffic)
// ===========================================================================
__global__ __launch_bounds__(128) void context_kernel(float* __restrict__ out)
{
    int b = blockIdx.z;
    int e0 = blockIdx.x * 256 + threadIdx.x * 2;
    int t0 = blockIdx.y * 256;
    const float* wrow = out + OUT_W + b*TT + t0;
    const __half* ep = g_Ahalf + ((size_t)b*TT + t0)*EP + e0;
    float s0 = 0.f, s1 = 0.f;
    #pragma unroll 8
    for (int t = 0; t < 256; t++) {
        float wv = __ldg(wrow + t);
        __half2 h = *reinterpret_cast<const __half2*>(ep + (size_t)t*EP);
        float2 v = __half22float2(h);
        s0 = fmaf(wv, v.x, s0);
        s1 = fmaf(wv, v.y, s1);
    }
    atomicAdd(&out[OUT_CV + b*EP + e0],     s0);
    atomicAdd(&out[OUT_CV + b*EP + e0 + 1], s1);
}

// ===========================================================================
extern "C" void kernel_launch(void* const* d_in, const int* in_sizes, int n_in,
                              void* d_out, int out_size)
{
    const float* enc      = (const float*)d_in[0];
    const int*   enc_len  = (const int*)  d_in[1];
    const float* dec_z    = (const float*)d_in[2];
    const float* att_prev = (const float*)d_in[3];
    const float* att_h    = (const float*)d_in[4];
    const float* att_c    = (const float*)d_in[5];
    const float* W_w      = (const float*)d_in[6];
    const float* W_b      = (const float*)d_in[7];
    const float* V_w      = (const float*)d_in[8];
    const float* V_b      = (const float*)d_in[9];
    const float* U_w      = (const float*)d_in[10];
    const float* U_b      = (const float*)d_in[11];
    const float* g_w      = (const float*)d_in[12];
    const float* g_b      = (const float*)d_in[13];  // unused: softmax shift-invariant
    const float* conv_w   = (const float*)d_in[14];
    const float* W_ih     = (const float*)d_in[15];
    const float* W_hh     = (const float*)d_in[16];
    const float* b_ih     = (const float*)d_in[17];
    const float* b_hh     = (const float*)d_in[18];
    float* out = (float*)d_out;
    (void)g_b;

    cudaFuncSetAttribute(score_mma_kernel, cudaFuncAttributeMaxDynamicSharedMemorySize, SCORE_SMEM);

    // K0: enc->fp16, V_w->fp16^T, zero g_score+c_v, g_gates/g_bias init, att_h^T
    convAB_kernel<<<(BSZ*TT*EP/4) / 256, 256>>>(enc, V_w, b_ih, b_hh, att_h,
                                                W_b, U_b, V_b, out);
    // K1: register-tiled conv + relu + maxpool -> featT (4 ch/block, 256 blocks)
    conv_max_kernel<<<dim3(BSZ, NCH/CG), 256>>>(att_prev, conv_w);
    // K2: LSTM gates (transposed, k-split, atomic)
    gates_kernel<<<1024, 256>>>(W_ih, W_hh);
    // K3: fused LSTM + bias, weight-stationary (256 blocks)
    lstm_bias_kernel<<<dim3(4, 16, BSZ/BG), 128>>>(att_c, dec_z, W_w, U_w, out);
    // K4: single-pass fp16 GEMM (f32 accum) + tanh/g-dot -> score
    score_mma_kernel<<<(BSZ*TT/128) * 4, 256, SCORE_SMEM>>>(g_w);
    // K5: masked scaled softmax -> w
    softmax_kernel<<<BSZ, 256>>>(enc_len, out);
    // K6: context vector (fp16 enc)
    context_kernel<<<dim3(2, 8, BSZ), 128>>>(out);
}